// round 16
// baseline (speedup 1.0000x reference)
#include <cuda_runtime.h>
#include <cuda_bf16.h>
#include <cstdint>

#define N_NODES 120000
#define N_EDGES 1000000
#define DIM 64
#define N_LAYERS 3
#define OUT_STRIDE 256   // (N_LAYERS+1)*DIM
#define NB 8             // nodes per warp (64 nodes per block)
#define SCAN_TB 1024
#define SCAN_BLOCKS ((N_NODES + SCAN_TB - 1) / SCAN_TB)  // 118

// ---------------- scratch ----------------
__device__ int   g_degcol[N_NODES];
__device__ int   g_degrow[N_NODES];
__device__ float g_dinv[N_NODES];
__device__ int   g_rowptr[N_NODES + 1];
__device__ int   g_cursor[N_NODES];
__device__ int   g_blocksum[SCAN_BLOCKS];
__device__ int2  g_edges[N_EDGES];                        // CSR {col*OUT_STRIDE, norm bits}
__device__ __align__(16) unsigned char g_wsw[3 * 32768];  // per layer: [Whi 16KB | Wlo 16KB], swizzled
__device__ float g_biasf[3 * DIM];

// ---------------- PTX helpers (baseline sm_80/90 features only) ----------------
__device__ __forceinline__ uint32_t smem_u32(const void* p) {
    uint32_t a;
    asm("{ .reg .u64 t; cvta.to.shared.u64 t, %1; cvt.u32.u64 %0, t; }" : "=r"(a) : "l"(p));
    return a;
}
#define CVT_BF16X2(res, a, b) \
    asm("cvt.rn.bf16x2.f32 %0, %1, %2;" : "=r"(res) : "f"(b), "f"(a))   // lo=bf16(a), hi=bf16(b)

#define MBARRIER_INIT(addr, cnt) \
    asm volatile("mbarrier.init.shared.b64 [%0], %1;" :: "r"(addr), "r"((uint32_t)(cnt)) : "memory")
#define MBARRIER_EXPECT_TX(addr, bytes) \
    asm volatile("mbarrier.arrive.expect_tx.shared.b64 _, [%0], %1;" :: "r"(addr), "r"((uint32_t)(bytes)) : "memory")
__device__ __forceinline__ void mbar_wait(uint32_t mbar, uint32_t parity) {
    asm volatile(
        "{\n\t.reg .pred P1;\n\t"
        "WL%=:\n\t"
        "mbarrier.try_wait.parity.shared.b64 P1, [%0], %1;\n\t"
        "@P1 bra.uni WD%=;\n\t"
        "bra.uni WL%=;\n\t"
        "WD%=:\n\t}"
        :: "r"(mbar), "r"(parity) : "memory");
}
#define BULK_CP(dst_smem, src_gmem, bytes, mbar) \
    asm volatile("cp.async.bulk.shared::cta.global.mbarrier::complete_tx::bytes [%0], [%1], %2, [%3];" \
                 :: "r"(dst_smem), "l"(src_gmem), "r"((uint32_t)(bytes)), "r"(mbar) : "memory")

#define LDSM_X4(r0, r1, r2, r3, addr) \
    asm volatile("ldmatrix.sync.aligned.m8n8.x4.shared.b16 {%0,%1,%2,%3}, [%4];" \
                 : "=r"(r0), "=r"(r1), "=r"(r2), "=r"(r3) : "r"(addr))
#define MMA16816(c0, c1, c2, c3, a0, a1, a2, a3, b0, b1) \
    asm volatile("mma.sync.aligned.m16n8k16.row.col.f32.bf16.bf16.f32 " \
                 "{%0,%1,%2,%3}, {%4,%5,%6,%7}, {%8,%9}, {%0,%1,%2,%3};" \
                 : "+f"(c0), "+f"(c1), "+f"(c2), "+f"(c3) \
                 : "r"(a0), "r"(a1), "r"(a2), "r"(a3), "r"(b0), "r"(b1))

// ---------------- setup kernels (proven R13) ----------------
__global__ void init_kernel() {
    int i = blockIdx.x * blockDim.x + threadIdx.x;
    if (i < N_NODES) { g_degcol[i] = 0; g_degrow[i] = 0; }
}

__global__ void hist_kernel(const int* __restrict__ ei) {
    int e = blockIdx.x * blockDim.x + threadIdx.x;
    if (e >= N_EDGES) return;
    atomicAdd(&g_degrow[ei[e]], 1);
    atomicAdd(&g_degcol[ei[N_EDGES + e]], 1);
}

__global__ void scan_a_kernel() {
    __shared__ int wsum[32];
    int tid = threadIdx.x, lane = tid & 31, wid = tid >> 5;
    int i = blockIdx.x * SCAN_TB + tid;
    if (i < N_NODES) {
        int d = g_degcol[i];
        g_dinv[i] = (d > 0) ? rsqrtf((float)d) : 0.f;
    }
    int v = (i < N_NODES) ? g_degrow[i] : 0;
    int x = v;
#pragma unroll
    for (int off = 1; off < 32; off <<= 1) {
        int y = __shfl_up_sync(0xffffffffu, x, off);
        if (lane >= off) x += y;
    }
    if (lane == 31) wsum[wid] = x;
    __syncthreads();
    if (wid == 0) {
        int w = wsum[lane];
#pragma unroll
        for (int off = 1; off < 32; off <<= 1) {
            int y = __shfl_up_sync(0xffffffffu, w, off);
            if (lane >= off) w += y;
        }
        wsum[lane] = w;
    }
    __syncthreads();
    int excl = ((wid > 0) ? wsum[wid - 1] : 0) + x - v;
    if (i < N_NODES) g_rowptr[i] = excl;
    if (tid == SCAN_TB - 1) g_blocksum[blockIdx.x] = excl + v;
}

__global__ void scan_b_kernel() {
    __shared__ int ws[4];
    int tid = threadIdx.x, lane = tid & 31, wid = tid >> 5;
    int v = (tid < SCAN_BLOCKS) ? g_blocksum[tid] : 0;
    int x = v;
#pragma unroll
    for (int off = 1; off < 32; off <<= 1) {
        int y = __shfl_up_sync(0xffffffffu, x, off);
        if (lane >= off) x += y;
    }
    if (lane == 31) ws[wid] = x;
    __syncthreads();
    int carry = 0;
    for (int k = 0; k < wid; k++) carry += ws[k];
    if (tid < SCAN_BLOCKS) g_blocksum[tid] = carry + x - v;
}

__global__ void scan_c_kernel() {
    int i = blockIdx.x * SCAN_TB + threadIdx.x;
    if (i < N_NODES) {
        int r = g_rowptr[i] + g_blocksum[blockIdx.x];
        g_rowptr[i] = r;
        g_cursor[i] = r;
    }
    if (i == 0) g_rowptr[N_NODES] = N_EDGES;
}

__global__ void scatter_kernel(const int* __restrict__ ei) {
    int e = blockIdx.x * blockDim.x + threadIdx.x;
    if (e >= N_EDGES) return;
    int r = ei[e];
    int c = ei[N_EDGES + e];
    float nv = g_dinv[r] * g_dinv[c];
    int pos = atomicAdd(&g_cursor[r], 1);
    g_edges[pos] = make_int2(c * OUT_STRIDE, __float_as_int(nv));
}

__global__ void copy_emb_kernel(const float* __restrict__ emb, float* __restrict__ out) {
    int i = blockIdx.x * blockDim.x + threadIdx.x;
    if (i >= N_NODES * (DIM / 4)) return;
    int r = i >> 4;
    int q = i & 15;
    ((float4*)out)[(size_t)r * (OUT_STRIDE / 4) + q] = ((const float4*)emb)[i];
}

// W prep: W'[d][k] (d=out row, k: 0-63 W1, 64-127 W2) split bf16 hi/lo, XOR-swizzled rows (256B).
__global__ void wprep_kernel(const float* __restrict__ W1, const float* __restrict__ b1,
                             const float* __restrict__ W2, const float* __restrict__ b2) {
    int i = blockIdx.x * blockDim.x + threadIdx.x;
    if (i < 3 * DIM) g_biasf[i] = b1[i] + b2[i];
    if (i >= 3 * 8192) return;
    int l = i >> 13;
    int idx = i & 8191;
    int d = idx >> 7, k = idx & 127;
    float w = (k < 64) ? W1[l * 4096 + d * 64 + k] : W2[l * 4096 + d * 64 + (k - 64)];
    __nv_bfloat16 h = __float2bfloat16(w);
    __nv_bfloat16 lo = __float2bfloat16(w - __bfloat162float(h));
    int off = d * 256 + (((k >> 3) ^ (d & 7)) << 4) + (k & 7) * 2;   // 16 chunks/row, XOR swizzle
    unsigned char* base = g_wsw + l * 32768;
    *(unsigned short*)(base + off) = *(unsigned short*)&h;
    *(unsigned short*)(base + 16384 + off) = *(unsigned short*)&lo;
}

// ---------------- fused layer: gather + bf16 split mma.sync + epilogue ----------------
// smem layout (bytes):
#define SM_W     0        // 32768: [Whi | Wlo], swizzled, bulk-copied
#define SM_A     32768    // 32768: A [64 rows x 512B] bf16: k 0-63 a1hi, 64-127 a2hi, 128-191 a1lo, 192-255 a2lo
#define SM_BIAS  65536    // 256
#define SM_SV    65792    // 256
#define SM_MB    66048    // 8
#define SM_TOTAL 66080

__global__ __launch_bounds__(256) void fused_layer_kernel(
    const unsigned char* __restrict__ wsw, const float* __restrict__ biasf,
    float* __restrict__ out, int loff) {
    extern __shared__ char smem[];
    uint32_t smem_base = smem_u32(smem);
    int tid = threadIdx.x;
    int lane = tid & 31;
    int wid = tid >> 5;

    if (tid == 0) MBARRIER_INIT(smem_base + SM_MB, 1);
    if (tid < DIM) ((float*)(smem + SM_BIAS))[tid] = biasf[tid];
    __syncthreads();
    if (tid == 0) {
        MBARRIER_EXPECT_TX(smem_base + SM_MB, 32768);
        BULK_CP(smem_base + SM_W, wsw, 32768, smem_base + SM_MB);
    }

    // ---- gather (R13-proven): warp wid owns rows [wid*8, wid*8+8); lane owns dims {2l, 2l+1} ----
    const float* x = out + loff;
    float* ssv = (float*)(smem + SM_SV);
    int base = blockIdx.x * 64;
#pragma unroll
    for (int j = 0; j < NB; j++) {
        int ln = wid * NB + j;
        int n = base + ln;
        float ax = 0.f, ay = 0.f, s = 0.f;
        int s0 = g_rowptr[n], s1 = g_rowptr[n + 1];
        float2 xr = *(const float2*)(x + (size_t)n * OUT_STRIDE + 2 * lane);
        int e = s0;
        for (; e + 2 <= s1; e += 2) {
            int2 rA = g_edges[e];
            int2 rB = g_edges[e + 1];
            float2 xA = *(const float2*)(x + rA.x + 2 * lane);
            float2 xB = *(const float2*)(x + rB.x + 2 * lane);
            float nA = __int_as_float(rA.y), nB = __int_as_float(rB.y);
            ax += nA * xA.x + nB * xB.x;
            ay += nA * xA.y + nB * xB.y;
            s += nA + nB;
        }
        if (e < s1) {
            int2 rc = g_edges[e];
            float nv = __int_as_float(rc.y);
            float2 xc = *(const float2*)(x + rc.x + 2 * lane);
            ax += nv * xc.x;
            ay += nv * xc.y;
            s += nv;
        }
        float a2x = ax * xr.x, a2y = ay * xr.y;
        // bf16 hi/lo split
        uint32_t h1, h2, l1, l2;
        CVT_BF16X2(h1, ax, ay);
        CVT_BF16X2(h2, a2x, a2y);
        float h1x = __uint_as_float(h1 << 16), h1y = __uint_as_float(h1 & 0xFFFF0000u);
        float h2x = __uint_as_float(h2 << 16), h2y = __uint_as_float(h2 & 0xFFFF0000u);
        CVT_BF16X2(l1, ax - h1x, ay - h1y);
        CVT_BF16X2(l2, a2x - h2x, a2y - h2y);
        // swizzled store into A: word w -> chunk (w>>2)^(ln&7), keep low 2 bits
        uint32_t* arow = (uint32_t*)(smem + SM_A + ln * 512);
        int sw = ln & 7;
        int w0 = lane,       c0 = ((w0 >> 2) ^ sw) * 4 + (w0 & 3);
        int w1 = 32 + lane,  c1 = ((w1 >> 2) ^ sw) * 4 + (w1 & 3);
        int w2 = 64 + lane,  c2 = ((w2 >> 2) ^ sw) * 4 + (w2 & 3);
        int w3 = 96 + lane,  c3 = ((w3 >> 2) ^ sw) * 4 + (w3 & 3);
        arow[c0] = h1;
        arow[c1] = h2;
        arow[c2] = l1;
        arow[c3] = l2;
        if (lane == 0) ssv[ln] = s;
    }
    __syncthreads();          // A + sv visible to all warps
    mbar_wait(smem_base + SM_MB, 0);   // W resident

    // ---- GEMM: warp (mi, ni) computes C[16 nodes x 32 d] ----
    int mi = wid >> 1, ni = wid & 1;
    int grp = lane >> 3;
    int arow_i = 16 * mi + ((grp & 1) << 3) + (lane & 7);
    uint32_t a_base = smem_base + SM_A + arow_i * 512;
    int aswz = arow_i & 7;
    int khi = lane >> 4;
    int drow = ni * 32 + lane;
    uint32_t b_base = smem_base + SM_W + drow * 256;
    int bswz = drow & 7;

    float c[16];
#pragma unroll
    for (int i = 0; i < 16; i++) c[i] = 0.f;

#pragma unroll
    for (int p = 0; p < 3; p++) {
        int abase = (p == 1) ? 16 : 0;             // lo A-cols on pass 1
        uint32_t woff = (p == 2) ? 16384u : 0u;    // Wlo on pass 2
#pragma unroll
        for (int s = 0; s < 8; s++) {
            uint32_t a0, a1, a2, a3, bl0, bl1, bl2, bl3, bh0, bh1, bh2, bh3;
            LDSM_X4(a0, a1, a2, a3,
                    a_base + (uint32_t)(((abase + 2 * s + khi) ^ aswz) << 4));
            // B fragment: non-trans — lane gets contiguous k-pair of its d-row (PTX B layout)
            LDSM_X4(bl0, bl1, bl2, bl3,
                    b_base + woff + (uint32_t)(((2 * s) ^ bswz) << 4));
            LDSM_X4(bh0, bh1, bh2, bh3,
                    b_base + woff + (uint32_t)(((2 * s + 1) ^ bswz) << 4));
            MMA16816(c[0],  c[1],  c[2],  c[3],  a0, a1, a2, a3, bl0, bh0);
            MMA16816(c[4],  c[5],  c[6],  c[7],  a0, a1, a2, a3, bl1, bh1);
            MMA16816(c[8],  c[9],  c[10], c[11], a0, a1, a2, a3, bl2, bh2);
            MMA16816(c[12], c[13], c[14], c[15], a0, a1, a2, a3, bl3, bh3);
        }
    }

    // ---- epilogue: C + sv*bias, LeakyReLU, store ----
    {
        const float* sbias = (const float*)(smem + SM_BIAS);
        int r0 = lane >> 2;
        int cc = (lane & 3) * 2;
        float svA = ssv[16 * mi + r0];
        float svB = ssv[16 * mi + r0 + 8];
        float* oA = out + (size_t)(base + 16 * mi + r0) * OUT_STRIDE + loff + DIM;
        float* oB = oA + 8 * OUT_STRIDE;
#pragma unroll
        for (int g = 0; g < 4; g++) {
            int d = ni * 32 + g * 8 + cc;
            float bx = sbias[d], by = sbias[d + 1];
            float vx = c[g * 4 + 0] + svA * bx;
            float vy = c[g * 4 + 1] + svA * by;
            float ux = c[g * 4 + 2] + svB * bx;
            float uy = c[g * 4 + 3] + svB * by;
            vx = vx >= 0.f ? vx : 0.2f * vx;
            vy = vy >= 0.f ? vy : 0.2f * vy;
            ux = ux >= 0.f ? ux : 0.2f * ux;
            uy = uy >= 0.f ? uy : 0.2f * uy;
            *(float2*)(oA + d) = make_float2(vx, vy);
            *(float2*)(oB + d) = make_float2(ux, uy);
        }
    }
}

// ---------------- launch ----------------
extern "C" void kernel_launch(void* const* d_in, const int* in_sizes, int n_in,
                              void* d_out, int out_size) {
    const int* edge_index = (const int*)d_in[0];   // [2,E] int32
    const float* emb = (const float*)d_in[1];
    const float* W1 = (const float*)d_in[2];
    const float* b1 = (const float*)d_in[3];
    const float* W2 = (const float*)d_in[4];
    const float* b2 = (const float*)d_in[5];
    float* out = (float*)d_out;

    unsigned char* p_wsw;
    float* p_biasf;
    cudaGetSymbolAddress((void**)&p_wsw, g_wsw);
    cudaGetSymbolAddress((void**)&p_biasf, g_biasf);

    const int TB = 256;
    const int NBLK = (N_NODES + TB - 1) / TB;
    const int EBLK = (N_EDGES + TB - 1) / TB;

    init_kernel<<<NBLK, TB>>>();
    hist_kernel<<<EBLK, TB>>>(edge_index);
    scan_a_kernel<<<SCAN_BLOCKS, SCAN_TB>>>();
    scan_b_kernel<<<1, 128>>>();
    scan_c_kernel<<<SCAN_BLOCKS, SCAN_TB>>>();
    scatter_kernel<<<EBLK, TB>>>(edge_index);
    copy_emb_kernel<<<(N_NODES * (DIM / 4) + TB - 1) / TB, TB>>>(emb, out);
    wprep_kernel<<<(3 * 8192 + TB - 1) / TB, TB>>>(W1, b1, W2, b2);

    cudaFuncSetAttribute(fused_layer_kernel, cudaFuncAttributeMaxDynamicSharedMemorySize, SM_TOTAL);
    const int FBLK = N_NODES / 64;  // 1875 exact
    for (int l = 0; l < N_LAYERS; l++) {
        fused_layer_kernel<<<FBLK, 256, SM_TOTAL>>>(
            p_wsw + l * 32768, p_biasf + l * DIM, out, l * DIM);
    }
}

// round 17
// speedup vs baseline: 1.2917x; 1.2917x over previous
#include <cuda_runtime.h>
#include <cstdint>

#define N_NODES 120000
#define N_EDGES 1000000
#define DIM 64
#define N_LAYERS 3
#define OUT_STRIDE 256   // (N_LAYERS+1)*DIM
#define NB 8             // nodes per warp
#define SCAN_TB 1024
#define SCAN_BLOCKS ((N_NODES + SCAN_TB - 1) / SCAN_TB)  // 118

typedef unsigned long long u64;

// ---------------- scratch ----------------
__device__ int   g_degcol[N_NODES];
__device__ int   g_degrow[N_NODES];
__device__ float g_dinv[N_NODES];
__device__ int   g_rowptr[N_NODES + 1];
__device__ int   g_cursor[N_NODES];
__device__ u64   g_scanstate[SCAN_BLOCKS];   // hi32: 0=none,1=aggregate,2=prefix; lo32: value
__device__ int2  g_edges[N_EDGES];           // CSR {col*64, __float_as_int(norm)}

// ---------------- packed f32x2 helpers (validated R13) ----------------
__device__ __forceinline__ u64 fma2(u64 a, u64 b, u64 c) {
    u64 d;
    asm("fma.rn.f32x2 %0, %1, %2, %3;" : "=l"(d) : "l"(a), "l"(b), "l"(c));
    return d;
}
__device__ __forceinline__ u64 pack2(float lo, float hi) {
    u64 d;
    asm("mov.b64 %0, {%1, %2};" : "=l"(d) : "f"(lo), "f"(hi));
    return d;
}
__device__ __forceinline__ float2 unpack2(u64 v) {
    float lo, hi;
    asm("mov.b64 {%0, %1}, %2;" : "=f"(lo), "=f"(hi) : "l"(v));
    return make_float2(lo, hi);
}

// ---------------- setup ----------------
__global__ void init_kernel() {
    int i = blockIdx.x * blockDim.x + threadIdx.x;
    if (i < N_NODES) { g_degcol[i] = 0; g_degrow[i] = 0; }
    if (i < SCAN_BLOCKS) g_scanstate[i] = 0ULL;
}

// 2 edges per thread
__global__ void hist_kernel(const int* __restrict__ ei) {
    int e2 = (blockIdx.x * blockDim.x + threadIdx.x) * 2;
    if (e2 >= N_EDGES) return;
    int2 rr = *(const int2*)(ei + e2);
    int2 cc = *(const int2*)(ei + N_EDGES + e2);
    atomicAdd(&g_degrow[rr.x], 1);
    atomicAdd(&g_degrow[rr.y], 1);
    atomicAdd(&g_degcol[cc.x], 1);
    atomicAdd(&g_degcol[cc.y], 1);
}

// single-kernel exclusive scan (decoupled lookback) + dinv finalize
__global__ void scan_kernel() {
    __shared__ int wsum[32];
    __shared__ int s_off;
    int tid = threadIdx.x, lane = tid & 31, wid = tid >> 5;
    int i = blockIdx.x * SCAN_TB + tid;
    if (i < N_NODES) {
        int d = g_degcol[i];
        g_dinv[i] = (d > 0) ? rsqrtf((float)d) : 0.f;
    }
    int v = (i < N_NODES) ? g_degrow[i] : 0;
    int x = v;
#pragma unroll
    for (int off = 1; off < 32; off <<= 1) {
        int y = __shfl_up_sync(0xffffffffu, x, off);
        if (lane >= off) x += y;
    }
    if (lane == 31) wsum[wid] = x;
    __syncthreads();
    if (wid == 0) {
        int w = wsum[lane];
#pragma unroll
        for (int off = 1; off < 32; off <<= 1) {
            int y = __shfl_up_sync(0xffffffffu, w, off);
            if (lane >= off) w += y;
        }
        wsum[lane] = w;
    }
    __syncthreads();
    int excl = ((wid > 0) ? wsum[wid - 1] : 0) + x - v;
    if (tid == 0) {
        int tot = wsum[31];
        int bid = blockIdx.x;
        u64 st = ((u64)((bid == 0) ? 2u : 1u) << 32) | (unsigned)tot;
        atomicExch(&g_scanstate[bid], st);
        int run = 0;
        if (bid > 0) {
            int b = bid - 1;
            while (true) {
                u64 s;
                do { s = atomicAdd(&g_scanstate[b], 0ULL); } while ((s >> 32) == 0ULL);
                run += (int)(s & 0xffffffffULL);
                if ((s >> 32) == 2ULL) break;
                b--;
            }
            atomicExch(&g_scanstate[bid], ((u64)2u << 32) | (unsigned)(run + tot));
        }
        s_off = run;
    }
    __syncthreads();
    if (i < N_NODES) {
        int r = s_off + excl;
        g_rowptr[i] = r;
        g_cursor[i] = r;
    }
    if (i == 0) g_rowptr[N_NODES] = N_EDGES;
}

// 2 edges per thread; col stored pre-scaled by 64 (layer stride applied via shift)
__global__ void scatter_kernel(const int* __restrict__ ei) {
    int e2 = (blockIdx.x * blockDim.x + threadIdx.x) * 2;
    if (e2 >= N_EDGES) return;
    int2 rr = *(const int2*)(ei + e2);
    int2 cc = *(const int2*)(ei + N_EDGES + e2);
    float nv0 = g_dinv[rr.x] * g_dinv[cc.x];
    float nv1 = g_dinv[rr.y] * g_dinv[cc.y];
    int p0 = atomicAdd(&g_cursor[rr.x], 1);
    g_edges[p0] = make_int2(cc.x * DIM, __float_as_int(nv0));
    int p1 = atomicAdd(&g_cursor[rr.y], 1);
    g_edges[p1] = make_int2(cc.y * DIM, __float_as_int(nv1));
}

// ---------------- fused layer: CSR gather + k-pair FFMA2 GEMV (R13-proven core) ----------------
// x = input features (row stride 64<<xshift); edge col offsets scale by <<xshift.
// If emb != nullptr (layer 0), block also copies its 64 emb rows into out cols [0,64).
__global__ __launch_bounds__(256, 3) void fused_layer_kernel(
    const float* __restrict__ W1, const float* __restrict__ b1,
    const float* __restrict__ W2, const float* __restrict__ b2,
    float* __restrict__ out, int ocol,
    const float* __restrict__ x, int xshift,
    const float* __restrict__ emb) {
    extern __shared__ char smem[];
    ulonglong2* sW1q = (ulonglong2*)smem;        // [g*32+l] = {W1[2l] k-pair, W1[2l+1] k-pair} 16KB
    ulonglong2* sW2q = sW1q + 32 * 32;           // 16KB
    float* sb = (float*)(sW2q + 32 * 32);        // 64 floats
    ulonglong2* sacc = (ulonglong2*)(sb + 64);   // [8 warps][NB][32 g] = 32KB

    int tid = threadIdx.x;
    int base = blockIdx.x * 64;

    if (emb) {   // layer 0: copy emb rows into out[:, 0:64)
        for (int t = tid; t < 1024; t += 256) {
            int r = t >> 4, q = t & 15;
            ((float4*)(out + (size_t)(base + r) * OUT_STRIDE))[q] =
                ((const float4*)(emb + (size_t)(base + r) * DIM))[q];
        }
    }
    {
        const float2* W1f = (const float2*)W1;   // [d][32] k-pairs
        const float2* W2f = (const float2*)W2;
        for (int i = tid; i < 1024; i += 256) {
            int g = i >> 5, l = i & 31;
            float2 w1a = W1f[(2 * l) * 32 + g];
            float2 w1b = W1f[(2 * l + 1) * 32 + g];
            float2 w2a = W2f[(2 * l) * 32 + g];
            float2 w2b = W2f[(2 * l + 1) * 32 + g];
            *(float4*)&sW1q[i] = make_float4(w1a.x, w1a.y, w1b.x, w1b.y);
            *(float4*)&sW2q[i] = make_float4(w2a.x, w2a.y, w2b.x, w2b.y);
        }
    }
    if (tid < DIM) sb[tid] = b1[tid] + b2[tid];
    __syncthreads();

    int lane = tid & 31;
    int w = tid >> 5;
    int nbase = base + w * NB;
    ulonglong2* macc = sacc + (size_t)w * (NB * 32);

    float sv[NB];
#pragma unroll
    for (int j = 0; j < NB; j++) {
        float ax = 0.f, ay = 0.f, s = 0.f;
        int n = nbase + j;
        int s0 = g_rowptr[n], s1 = g_rowptr[n + 1];
        float2 xr = *(const float2*)(x + ((size_t)n << (6 + xshift)) + 2 * lane);
        int e = s0;
        for (; e + 2 <= s1; e += 2) {   // two independent rec->x chains
            int2 rA = g_edges[e];
            int2 rB = g_edges[e + 1];
            float2 xA = *(const float2*)(x + ((size_t)rA.x << xshift) + 2 * lane);
            float2 xB = *(const float2*)(x + ((size_t)rB.x << xshift) + 2 * lane);
            float nA = __int_as_float(rA.y), nB = __int_as_float(rB.y);
            ax += nA * xA.x + nB * xB.x;
            ay += nA * xA.y + nB * xB.y;
            s += nA + nB;
        }
        if (e < s1) {
            int2 rc = g_edges[e];
            float nv = __int_as_float(rc.y);
            float2 xc = *(const float2*)(x + ((size_t)rc.x << xshift) + 2 * lane);
            ax += nv * xc.x;
            ay += nv * xc.y;
            s += nv;
        }
        sv[j] = s;
        // lane l owns k-group g=l: (a1[2l], a1[2l+1], a2[2l], a2[2l+1]) — one STS.128
        *(float4*)&macc[j * 32 + lane] = make_float4(ax, ay, ax * xr.x, ay * xr.y);
    }
    __syncwarp();

    float2 bf = *(const float2*)&sb[2 * lane];
    u64 p0[NB], p1[NB];
#pragma unroll
    for (int j = 0; j < NB; j++) {
        p0[j] = pack2(sv[j] * bf.x, 0.f);
        p1[j] = pack2(sv[j] * bf.y, 0.f);
    }

#pragma unroll 4
    for (int g = 0; g < 32; g++) {
        ulonglong2 w1 = sW1q[g * 32 + lane];   // LDS.128, conflict-free
        ulonglong2 w2 = sW2q[g * 32 + lane];
#pragma unroll
        for (int j = 0; j < NB; j++) {
            ulonglong2 aa = macc[j * 32 + g];  // LDS.128 broadcast: {a1 pair, a2 pair}
            p0[j] = fma2(aa.x, w1.x, p0[j]);
            p0[j] = fma2(aa.y, w2.x, p0[j]);
            p1[j] = fma2(aa.x, w1.y, p1[j]);
            p1[j] = fma2(aa.y, w2.y, p1[j]);
        }
    }

#pragma unroll
    for (int j = 0; j < NB; j++) {
        int n = nbase + j;
        float2 q0 = unpack2(p0[j]);
        float2 q1 = unpack2(p1[j]);
        float vx = q0.x + q0.y;
        float vy = q1.x + q1.y;
        vx = vx >= 0.f ? vx : 0.2f * vx;
        vy = vy >= 0.f ? vy : 0.2f * vy;
        *(float2*)(out + (size_t)n * OUT_STRIDE + ocol + 2 * lane) = make_float2(vx, vy);
    }
}

// ---------------- launch ----------------
extern "C" void kernel_launch(void* const* d_in, const int* in_sizes, int n_in,
                              void* d_out, int out_size) {
    const int* edge_index = (const int*)d_in[0];   // [2,E] int32
    const float* emb = (const float*)d_in[1];
    const float* W1 = (const float*)d_in[2];
    const float* b1 = (const float*)d_in[3];
    const float* W2 = (const float*)d_in[4];
    const float* b2 = (const float*)d_in[5];
    float* out = (float*)d_out;

    const int TB = 256;
    const int NBLK = (N_NODES + TB - 1) / TB;
    const int EBLK2 = (N_EDGES / 2 + TB - 1) / TB;

    init_kernel<<<NBLK, TB>>>();
    hist_kernel<<<EBLK2, TB>>>(edge_index);
    scan_kernel<<<SCAN_BLOCKS, SCAN_TB>>>();
    scatter_kernel<<<EBLK2, TB>>>(edge_index);

    // dynamic smem: weights 32 KB + bias 256B + acc staging 32 KB = 64.25 KB -> 3 blocks/SM
    const int SMEM_BYTES = 32 * 32 * 16 * 2 + 256 + 8 * NB * 32 * 16;  // 65792
    cudaFuncSetAttribute(fused_layer_kernel, cudaFuncAttributeMaxDynamicSharedMemorySize, SMEM_BYTES);

    const int FBLK = N_NODES / 64;  // 1875 exact
    // layer 0: x = emb (stride 64, xshift 0), also copies emb into out cols [0,64)
    fused_layer_kernel<<<FBLK, 256, SMEM_BYTES>>>(
        W1, b1, W2, b2, out, DIM, emb, 0, emb);
    // layers 1..2: x = out + l*64 (stride 256, xshift 2)
    for (int l = 1; l < N_LAYERS; l++) {
        fused_layer_kernel<<<FBLK, 256, SMEM_BYTES>>>(
            W1 + l * DIM * DIM, b1 + l * DIM,
            W2 + l * DIM * DIM, b2 + l * DIM,
            out, (l + 1) * DIM, out + l * DIM, 2, nullptr);
    }
}